// round 13
// baseline (speedup 1.0000x reference)
#include <cuda_runtime.h>
#include <math.h>
#include <stdint.h>

#define N_TIME   8192
#define NBANDS   128
#define THREADS  512
#define NWARPS   (THREADS / 32)     // 16
#define NF4      (N_TIME / 4)       // 2048 float4 per row
#define ITERS    4                  // float4 groups per lane

// MUFU EX2/LG2 via inline PTX (fast approx path).
__device__ __forceinline__ float ex2f(float x) {
    float y;
    asm("ex2.approx.ftz.f32 %0, %1;" : "=f"(y) : "f"(x));
    return y;
}
__device__ __forceinline__ float lg2f(float x) {
    float y;
    asm("lg2.approx.ftz.f32 %0, %1;" : "=f"(y) : "f"(x));
    return y;
}

// Packed f32x2 ops (Blackwell sm_103a; FFMA2 reachable only via PTX f32x2).
__device__ __forceinline__ uint64_t pk2(float lo, float hi) {
    uint64_t r;
    asm("mov.b64 %0, {%1, %2};" : "=l"(r) : "f"(lo), "f"(hi));
    return r;
}
__device__ __forceinline__ void upk2(float& lo, float& hi, uint64_t v) {
    asm("mov.b64 {%0, %1}, %2;" : "=f"(lo), "=f"(hi) : "l"(v));
}
__device__ __forceinline__ uint64_t fma2(uint64_t a, uint64_t b, uint64_t c) {
    uint64_t d;
    asm("fma.rn.f32x2 %0, %1, %2, %3;" : "=l"(d) : "l"(a), "l"(b), "l"(c));
    return d;
}
__device__ __forceinline__ uint64_t mul2(uint64_t a, uint64_t b) {
    uint64_t d;
    asm("mul.rn.f32x2 %0, %1, %2;" : "=l"(d) : "l"(a), "l"(b));
    return d;
}

__global__ void __launch_bounds__(THREADS, 2)
mrpcen_kernel(const float* __restrict__ x,
              const float* __restrict__ log_alpha,
              const float* __restrict__ log_delta,
              const float* __restrict__ log_r,
              float* __restrict__ out,
              float4 sv, int nbands)
{
    __shared__ float warp_tot[4][NWARPS];
    __shared__ float warp_excl[4][NWARPS];

    const int row  = blockIdx.x;              // b*F + f
    const int b    = row / nbands;
    const int f    = row % nbands;
    const int lane = threadIdx.x & 31;
    const int warp = threadIdx.x >> 5;

    const float4* __restrict__ xrow4 =
        reinterpret_cast<const float4*>(x) + (size_t)row * NF4;

    const float L2E = 1.4426950408889634f;    // log2(e)
    const float LN2 = 0.6931471805599453f;

    const float m0    = __ldg(x + (size_t)row * N_TIME);   // m[-1] = x[0]
    const float lgd   = __ldg(log_delta + f);              // ln(delta)
    const float alpha = ex2f(L2E * __ldg(log_alpha + f));
    const float rr    = ex2f(L2E * __ldg(log_r + f));
    const float dr    = ex2f(rr * lgd * L2E);              // delta^r
    const float nl2d  = -lgd * L2E;                        // -log2(delta)
    const float cr    = rr * LN2;                          // r*ln2

    // Pre-scaled Taylor coefficients for p~(z') = expm1(cr*z')/(cr*z'):
    //   p~ = 1 + (cr/2) z' + (cr^2/6) z'^2 + (cr^3/24) z'^3 + (cr^4/120) z'^4
    // out = (dr*cr) * z' * p~(z'), with z' = lg2(1 + w).
    const float cr2 = cr * cr;
    const uint64_t K1 = pk2(cr * 0.5f,            cr * 0.5f);
    const uint64_t K2 = pk2(cr2 * (1.f/6.f),      cr2 * (1.f/6.f));
    const uint64_t K3 = pk2(cr2 * cr * (1.f/24.f), cr2 * cr * (1.f/24.f));
    const uint64_t K4 = pk2(cr2 * cr2 * (1.f/120.f), cr2 * cr2 * (1.f/120.f));
    const uint64_t ONE2  = pk2(1.0f, 1.0f);
    const uint64_t DRCR2 = pk2(dr * cr, dr * cr);

    // per-rate constants: s, q, A = q^4 (group multiplier), lg2(q)
    float s[4], q[4], A[4], lg2q[4];
    #pragma unroll
    for (int t = 0; t < 4; t++) {
        s[t] = (t == 0) ? sv.x : (t == 1) ? sv.y : (t == 2) ? sv.z : sv.w;
        q[t] = 1.0f - s[t];
        float q2 = q[t] * q[t];
        A[t] = q2 * q2;               // q^4 exact
        lg2q[t] = lg2f(q[t]);         // finite: q in (0,1]
    }

    // ---- phase 1: coalesced loads + per-group affine reduction ----
    float c[4][ITERS];                // [rate][iter] group contributions
    #pragma unroll
    for (int i = 0; i < ITERS; i++) {
        const float4 v = __ldg(xrow4 + warp * 128 + i * 32 + lane);
        #pragma unroll
        for (int t = 0; t < 4; t++) {
            float cc = s[t] * v.x;
            cc = fmaf(q[t], cc, s[t] * v.y);
            cc = fmaf(q[t], cc, s[t] * v.z);
            cc = fmaf(q[t], cc, s[t] * v.w);
            c[t][i] = cc;
        }
    }

    // ---- phase 2: per rate, 4 independent warp scans over lanes ----
    float E[4][ITERS];     // exclusive within-iteration prefix
    float T[4][ITERS];     // iteration-tile totals (broadcast)
    float B[4];            // A^32 = q^128 (tile multiplier)
    #pragma unroll
    for (int t = 0; t < 4; t++) {
        float S0 = c[t][0], S1 = c[t][1], S2 = c[t][2], S3 = c[t][3];
        float P = A[t];
        #pragma unroll
        for (int o = 1; o < 32; o <<= 1) {
            float v0 = __shfl_up_sync(0xffffffffu, S0, o);
            float v1 = __shfl_up_sync(0xffffffffu, S1, o);
            float v2 = __shfl_up_sync(0xffffffffu, S2, o);
            float v3 = __shfl_up_sync(0xffffffffu, S3, o);
            if (lane >= o) {
                S0 = fmaf(P, v0, S0); S1 = fmaf(P, v1, S1);
                S2 = fmaf(P, v2, S2); S3 = fmaf(P, v3, S3);
            }
            P *= P;                   // after loop: P = A^32
        }
        B[t] = P;
        E[t][0] = __shfl_up_sync(0xffffffffu, S0, 1);
        E[t][1] = __shfl_up_sync(0xffffffffu, S1, 1);
        E[t][2] = __shfl_up_sync(0xffffffffu, S2, 1);
        E[t][3] = __shfl_up_sync(0xffffffffu, S3, 1);
        if (lane == 0) { E[t][0] = 0.f; E[t][1] = 0.f; E[t][2] = 0.f; E[t][3] = 0.f; }
        T[t][0] = __shfl_sync(0xffffffffu, S0, 31);
        T[t][1] = __shfl_sync(0xffffffffu, S1, 31);
        T[t][2] = __shfl_sync(0xffffffffu, S2, 31);
        T[t][3] = __shfl_sync(0xffffffffu, S3, 31);
        float U = fmaf(P, fmaf(P, fmaf(P, T[t][0], T[t][1]), T[t][2]), T[t][3]);
        if (lane == 0) warp_tot[t][warp] = U;
    }
    __syncthreads();

    // ---- phase 3: block scan over 16 warp totals per rate (mult D=B^4) ----
    if (warp == 0) {
        float W[4], Pq[4];
        #pragma unroll
        for (int t = 0; t < 4; t++) {
            W[t]  = (lane < NWARPS) ? warp_tot[t][lane] : 0.0f;
            float B2 = B[t] * B[t];
            Pq[t] = B2 * B2;          // D = q^512 (may flush to 0: OK)
        }
        #pragma unroll
        for (int o = 1; o < NWARPS; o <<= 1) {
            #pragma unroll
            for (int t = 0; t < 4; t++) {
                float v = __shfl_up_sync(0xffffffffu, W[t], o);
                if (lane >= o) W[t] = fmaf(Pq[t], v, W[t]);
                Pq[t] *= Pq[t];
            }
        }
        #pragma unroll
        for (int t = 0; t < 4; t++) {
            float Wex = __shfl_up_sync(0xffffffffu, W[t], 1);
            if (lane == 0) Wex = 0.0f;
            if (lane < NWARPS) warp_excl[t][lane] = Wex;
        }
    }
    __syncthreads();

    // ---- collapse carry state: C0[t][i] = carry entering my group ----
    float C0[4][ITERS];
    #pragma unroll
    for (int t = 0; t < 4; t++) {
        const float Bt = B[t];
        const float Dw = ex2f((float)(warp * 512) * lg2q[t]);  // q^(512*warp)
        float M0 = fmaf(Dw, m0, warp_excl[t][warp]);
        float M1 = fmaf(Bt, M0, T[t][0]);
        float M2 = fmaf(Bt, M1, T[t][1]);
        float M3 = fmaf(Bt, M2, T[t][2]);
        const float Al = ex2f((float)(lane * 4) * lg2q[t]);
        C0[t][0] = fmaf(Al, M0, E[t][0]);
        C0[t][1] = fmaf(Al, M1, E[t][1]);
        C0[t][2] = fmaf(Al, M2, E[t][2]);
        C0[t][3] = fmaf(Al, M3, E[t][3]);
    }

    const float nalpha = -alpha;

    // ---- phase 4: fused emit — one x load per group, 4 rates interleaved,
    // scalar MUFU front-end + packed f32x2 polynomial tail ----
    float4* __restrict__ obase = reinterpret_cast<float4*>(out) +
        ((size_t)b * 4 * nbands + f) * NF4;
    const size_t ostride = (size_t)nbands * NF4;     // float4 per rate plane

    #pragma unroll
    for (int i = 0; i < ITERS; i++) {
        const int g = warp * 128 + i * 32 + lane;
        const float4 xi4 = __ldg(xrow4 + g);         // single load per group

        #pragma unroll
        for (int tv = 0; tv < 4; tv++) {
            const float st = s[tv];
            const float qt = q[tv];
            float cy = C0[tv][i];

            // scalar front-end (MUFU-bound part): z'_k = lg2(1 + w_k)
            float zp[4];
            #pragma unroll
            for (int k = 0; k < 4; k++) {
                const float xi = (&xi4.x)[k];
                cy = fmaf(qt, cy, st * xi);
                const float u = 1e-5f + cy;                        // EPS + m
                const float w = xi * ex2f(fmaf(nalpha, lg2f(u), nl2d));
                zp[k] = lg2f(1.0f + w);
            }

            // packed tail: out = (dr*cr) * z' * p~(z')
            const uint64_t z01 = pk2(zp[0], zp[1]);
            const uint64_t z23 = pk2(zp[2], zp[3]);
            uint64_t p01 = fma2(K4, z01, K3);
            uint64_t p23 = fma2(K4, z23, K3);
            p01 = fma2(p01, z01, K2);  p23 = fma2(p23, z23, K2);
            p01 = fma2(p01, z01, K1);  p23 = fma2(p23, z23, K1);
            p01 = fma2(p01, z01, ONE2); p23 = fma2(p23, z23, ONE2);
            const uint64_t r01 = mul2(DRCR2, mul2(z01, p01));
            const uint64_t r23 = mul2(DRCR2, mul2(z23, p23));

            float4 o4;
            upk2(o4.x, o4.y, r01);
            upk2(o4.z, o4.w, r23);
            obase[(size_t)tv * ostride + g] = o4;      // coalesced STG.128
        }
    }
}

extern "C" void kernel_launch(void* const* d_in, const int* in_sizes, int n_in,
                              void* d_out, int out_size)
{
    const float* x  = (const float*)d_in[0];
    const float* la = (const float*)d_in[1];
    const float* ld = (const float*)d_in[2];
    const float* lr = (const float*)d_in[3];
    float* out = (float*)d_out;

    const int nbands = in_sizes[1];                 // 128
    const int rows   = in_sizes[0] / N_TIME;        // B * F = 1024

    // s = (sqrt(1 + 4 t^2) - 1) / (2 t^2), computed in double on host
    const double tvals[4] = {2.0, 8.0, 32.0, 128.0};
    float ss[4];
    for (int i = 0; i < 4; i++) {
        double t = tvals[i];
        ss[i] = (float)((sqrt(1.0 + 4.0 * t * t) - 1.0) / (2.0 * t * t));
    }
    float4 sv = make_float4(ss[0], ss[1], ss[2], ss[3]);

    mrpcen_kernel<<<rows, THREADS>>>(x, la, ld, lr, out, sv, nbands);
}

// round 14
// speedup vs baseline: 1.0586x; 1.0586x over previous
#include <cuda_runtime.h>
#include <math.h>

#define N_TIME   8192
#define NBANDS   128
#define THREADS  512
#define NWARPS   (THREADS / 32)     // 16
#define NF4      (N_TIME / 4)       // 2048 float4 per row
#define ITERS    4                  // float4 groups per lane

// MUFU EX2/LG2 via inline PTX (fast approx path).
__device__ __forceinline__ float ex2f(float x) {
    float y;
    asm("ex2.approx.ftz.f32 %0, %1;" : "=f"(y) : "f"(x));
    return y;
}
__device__ __forceinline__ float lg2f(float x) {
    float y;
    asm("lg2.approx.ftz.f32 %0, %1;" : "=f"(y) : "f"(x));
    return y;
}

__global__ void __launch_bounds__(THREADS, 2)
mrpcen_kernel(const float* __restrict__ x,
              const float* __restrict__ log_alpha,
              const float* __restrict__ log_delta,
              const float* __restrict__ log_r,
              float* __restrict__ out,
              float4 sv, int nbands)
{
    __shared__ float warp_tot[4][NWARPS];
    __shared__ float warp_excl[4][NWARPS];

    const int row  = blockIdx.x;              // b*F + f
    const int b    = row / nbands;
    const int f    = row % nbands;
    const int lane = threadIdx.x & 31;
    const int warp = threadIdx.x >> 5;

    const float4* __restrict__ xrow4 =
        reinterpret_cast<const float4*>(x) + (size_t)row * NF4;

    const float L2E = 1.4426950408889634f;    // log2(e)
    const float LN2 = 0.6931471805599453f;

    const float m0    = __ldg(x + (size_t)row * N_TIME);   // m[-1] = x[0]
    const float lgd   = __ldg(log_delta + f);              // ln(delta)
    const float alpha = ex2f(L2E * __ldg(log_alpha + f));
    const float rr    = ex2f(L2E * __ldg(log_r + f));
    const float dr    = ex2f(rr * lgd * L2E);              // delta^r
    const float nl2d  = -lgd * L2E;                        // -log2(delta)
    const float cr    = rr * LN2;                          // r*ln2

    // Pre-scaled Taylor coefficients for p~(z') = expm1(cr*z')/(cr*z'):
    //   p~ = 1 + (cr/2) z' + (cr^2/6) z'^2 + (cr^3/24) z'^3 + (cr^4/120) z'^4
    // out = (dr*cr) * z' * p~(z'), with z' = lg2(1 + w).
    // (4-term tail empirically sufficient: R13 measured rel_err 1.32e-6.)
    const float cr2  = cr * cr;
    const float K1   = cr * 0.5f;
    const float K2   = cr2 * (1.f / 6.f);
    const float K3   = cr2 * cr * (1.f / 24.f);
    const float K4   = cr2 * cr2 * (1.f / 120.f);
    const float drcr = dr * cr;

    // per-rate constants: s, q, A = q^4 (group multiplier), lg2(q)
    float s[4], q[4], A[4], lg2q[4];
    #pragma unroll
    for (int t = 0; t < 4; t++) {
        s[t] = (t == 0) ? sv.x : (t == 1) ? sv.y : (t == 2) ? sv.z : sv.w;
        q[t] = 1.0f - s[t];
        float q2 = q[t] * q[t];
        A[t] = q2 * q2;               // q^4 exact
        lg2q[t] = lg2f(q[t]);         // finite: q in (0,1]
    }

    // ---- phase 1: coalesced loads + per-group affine reduction ----
    // warp-tile layout: float4 index g(i) = warp*128 + i*32 + lane
    float c[4][ITERS];                // [rate][iter] group contributions
    #pragma unroll
    for (int i = 0; i < ITERS; i++) {
        const float4 v = __ldg(xrow4 + warp * 128 + i * 32 + lane);
        #pragma unroll
        for (int t = 0; t < 4; t++) {
            float cc = s[t] * v.x;
            cc = fmaf(q[t], cc, s[t] * v.y);
            cc = fmaf(q[t], cc, s[t] * v.z);
            cc = fmaf(q[t], cc, s[t] * v.w);
            c[t][i] = cc;
        }
    }

    // ---- phase 2: per rate, 4 independent warp scans over lanes ----
    float E[4][ITERS];     // exclusive within-iteration prefix
    float T[4][ITERS];     // iteration-tile totals (broadcast)
    float B[4];            // A^32 = q^128 (tile multiplier)
    #pragma unroll
    for (int t = 0; t < 4; t++) {
        float S0 = c[t][0], S1 = c[t][1], S2 = c[t][2], S3 = c[t][3];
        float P = A[t];
        #pragma unroll
        for (int o = 1; o < 32; o <<= 1) {
            float v0 = __shfl_up_sync(0xffffffffu, S0, o);
            float v1 = __shfl_up_sync(0xffffffffu, S1, o);
            float v2 = __shfl_up_sync(0xffffffffu, S2, o);
            float v3 = __shfl_up_sync(0xffffffffu, S3, o);
            if (lane >= o) {
                S0 = fmaf(P, v0, S0); S1 = fmaf(P, v1, S1);
                S2 = fmaf(P, v2, S2); S3 = fmaf(P, v3, S3);
            }
            P *= P;                   // after loop: P = A^32
        }
        B[t] = P;
        E[t][0] = __shfl_up_sync(0xffffffffu, S0, 1);
        E[t][1] = __shfl_up_sync(0xffffffffu, S1, 1);
        E[t][2] = __shfl_up_sync(0xffffffffu, S2, 1);
        E[t][3] = __shfl_up_sync(0xffffffffu, S3, 1);
        if (lane == 0) { E[t][0] = 0.f; E[t][1] = 0.f; E[t][2] = 0.f; E[t][3] = 0.f; }
        T[t][0] = __shfl_sync(0xffffffffu, S0, 31);
        T[t][1] = __shfl_sync(0xffffffffu, S1, 31);
        T[t][2] = __shfl_sync(0xffffffffu, S2, 31);
        T[t][3] = __shfl_sync(0xffffffffu, S3, 31);
        // warp-tile total U = T3 + B*T2 + B^2*T1 + B^3*T0
        float U = fmaf(P, fmaf(P, fmaf(P, T[t][0], T[t][1]), T[t][2]), T[t][3]);
        if (lane == 0) warp_tot[t][warp] = U;
    }
    __syncthreads();

    // ---- phase 3: block scan over 16 warp totals per rate (mult D=B^4) ----
    // Dt = q^512 may underflow to 0 for fast rates; numerically correct.
    if (warp == 0) {
        float W[4], Pq[4];
        #pragma unroll
        for (int t = 0; t < 4; t++) {
            W[t]  = (lane < NWARPS) ? warp_tot[t][lane] : 0.0f;
            float B2 = B[t] * B[t];
            Pq[t] = B2 * B2;          // D = q^512 (may flush to 0: OK)
        }
        #pragma unroll
        for (int o = 1; o < NWARPS; o <<= 1) {
            #pragma unroll
            for (int t = 0; t < 4; t++) {
                float v = __shfl_up_sync(0xffffffffu, W[t], o);
                if (lane >= o) W[t] = fmaf(Pq[t], v, W[t]);
                Pq[t] *= Pq[t];
            }
        }
        #pragma unroll
        for (int t = 0; t < 4; t++) {
            float Wex = __shfl_up_sync(0xffffffffu, W[t], 1);
            if (lane == 0) Wex = 0.0f;
            if (lane < NWARPS) warp_excl[t][lane] = Wex;
        }
    }
    __syncthreads();

    // ---- collapse carry state: C0[t][i] = carry entering my group ----
    float C0[4][ITERS];
    #pragma unroll
    for (int t = 0; t < 4; t++) {
        const float Bt = B[t];
        const float Dw = ex2f((float)(warp * 512) * lg2q[t]);  // q^(512*warp)
        float M0 = fmaf(Dw, m0, warp_excl[t][warp]);
        float M1 = fmaf(Bt, M0, T[t][0]);
        float M2 = fmaf(Bt, M1, T[t][1]);
        float M3 = fmaf(Bt, M2, T[t][2]);
        const float Al = ex2f((float)(lane * 4) * lg2q[t]);
        C0[t][0] = fmaf(Al, M0, E[t][0]);
        C0[t][1] = fmaf(Al, M1, E[t][1]);
        C0[t][2] = fmaf(Al, M2, E[t][2]);
        C0[t][3] = fmaf(Al, M3, E[t][3]);
    }

    const float nalpha = -alpha;

    // ---- phase 4: fused emit — one x load per group, 4 rates interleaved ----
    // out = (dr*cr) * z' * p~(z'), z' = lg2(1 + x*sm/d)
    float4* __restrict__ obase = reinterpret_cast<float4*>(out) +
        ((size_t)b * 4 * nbands + f) * NF4;
    const size_t ostride = (size_t)nbands * NF4;     // float4 per rate plane

    #pragma unroll
    for (int i = 0; i < ITERS; i++) {
        const int g = warp * 128 + i * 32 + lane;
        const float4 xi4 = __ldg(xrow4 + g);         // single load per group

        #pragma unroll
        for (int tv = 0; tv < 4; tv++) {
            const float st = s[tv];
            const float qt = q[tv];
            float cy = C0[tv][i];
            float4 o4;
            #pragma unroll
            for (int k = 0; k < 4; k++) {
                const float xi = (&xi4.x)[k];
                cy = fmaf(qt, cy, st * xi);
                const float u  = 1e-5f + cy;                        // EPS + m
                // w = x * (EPS+m)^-a / d  (1/d folded into the exponent)
                const float w  = xi * ex2f(fmaf(nalpha, lg2f(u), nl2d));
                const float zp = lg2f(1.0f + w);
                // p~(z') with cr-folded coefficients (FMA pipe)
                float p = fmaf(K4, zp, K3);
                p = fmaf(p, zp, K2);
                p = fmaf(p, zp, K1);
                p = fmaf(p, zp, 1.0f);
                (&o4.x)[k] = drcr * (zp * p);          // d^r * expm1(r ln(1+w))
            }
            obase[(size_t)tv * ostride + g] = o4;      // coalesced STG.128
        }
    }
}

extern "C" void kernel_launch(void* const* d_in, const int* in_sizes, int n_in,
                              void* d_out, int out_size)
{
    const float* x  = (const float*)d_in[0];
    const float* la = (const float*)d_in[1];
    const float* ld = (const float*)d_in[2];
    const float* lr = (const float*)d_in[3];
    float* out = (float*)d_out;

    const int nbands = in_sizes[1];                 // 128
    const int rows   = in_sizes[0] / N_TIME;        // B * F = 1024

    // s = (sqrt(1 + 4 t^2) - 1) / (2 t^2), computed in double on host
    const double tvals[4] = {2.0, 8.0, 32.0, 128.0};
    float ss[4];
    for (int i = 0; i < 4; i++) {
        double t = tvals[i];
        ss[i] = (float)((sqrt(1.0 + 4.0 * t * t) - 1.0) / (2.0 * t * t));
    }
    float4 sv = make_float4(ss[0], ss[1], ss[2], ss[3]);

    mrpcen_kernel<<<rows, THREADS>>>(x, la, ld, lr, out, sv, nbands);
}

// round 15
// speedup vs baseline: 1.0911x; 1.0306x over previous
#include <cuda_runtime.h>
#include <math.h>

#define N_TIME   8192
#define NBANDS   128
#define THREADS  512
#define NWARPS   (THREADS / 32)     // 16
#define NF4      (N_TIME / 4)       // 2048 float4 per row
#define ITERS    4                  // float4 groups per lane

// MUFU EX2/LG2 via inline PTX (fast approx path).
__device__ __forceinline__ float ex2f(float x) {
    float y;
    asm("ex2.approx.ftz.f32 %0, %1;" : "=f"(y) : "f"(x));
    return y;
}
__device__ __forceinline__ float lg2f(float x) {
    float y;
    asm("lg2.approx.ftz.f32 %0, %1;" : "=f"(y) : "f"(x));
    return y;
}

__global__ void __launch_bounds__(THREADS, 2)
mrpcen_kernel(const float* __restrict__ x,
              const float* __restrict__ log_alpha,
              const float* __restrict__ log_delta,
              const float* __restrict__ log_r,
              float* __restrict__ out,
              float4 sv, int nbands)
{
    __shared__ float warp_tot[4][NWARPS];
    __shared__ float warp_excl[4][NWARPS];

    const int row  = blockIdx.x;              // b*F + f
    const int b    = row / nbands;
    const int f    = row % nbands;
    const int lane = threadIdx.x & 31;
    const int warp = threadIdx.x >> 5;

    const float4* __restrict__ xrow4 =
        reinterpret_cast<const float4*>(x) + (size_t)row * NF4;

    const float L2E = 1.4426950408889634f;    // log2(e)
    const float LN2 = 0.6931471805599453f;

    const float m0    = __ldg(x + (size_t)row * N_TIME);   // m[-1] = x[0]
    const float lgd   = __ldg(log_delta + f);              // ln(delta)
    const float alpha = ex2f(L2E * __ldg(log_alpha + f));
    const float rr    = ex2f(L2E * __ldg(log_r + f));
    const float dr    = ex2f(rr * lgd * L2E);              // delta^r
    const float nl2d  = -lgd * L2E;                        // -log2(delta)
    const float cr    = rr * LN2;                          // r*ln2

    // Taylor for out = (dr*cr) * z' * p~(z'), z' = lg2(1+w),
    // with dr*cr folded into the coefficients:
    //   out = z' * (G0 + G1 z' + G2 z'^2 + G3 z'^3 + G4 z'^4)
    //   Gn = dr*cr * cr^n / (n+1)!
    // (4-term tail empirically sufficient: R13/R14 measured rel_err 1.3e-6.)
    const float drcr = dr * cr;
    const float cr2  = cr * cr;
    const float G0   = drcr;
    const float G1   = drcr * cr * 0.5f;
    const float G2   = drcr * cr2 * (1.f / 6.f);
    const float G3   = drcr * cr2 * cr * (1.f / 24.f);
    const float G4   = drcr * cr2 * cr2 * (1.f / 120.f);

    // per-rate constants: s, q, A = q^4 (group multiplier), lg2(q), m0/s
    float s[4], q[4], A[4], lg2q[4], m0s[4];
    #pragma unroll
    for (int t = 0; t < 4; t++) {
        s[t] = (t == 0) ? sv.x : (t == 1) ? sv.y : (t == 2) ? sv.z : sv.w;
        q[t] = 1.0f - s[t];
        float q2 = q[t] * q[t];
        A[t] = q2 * q2;               // q^4 exact
        lg2q[t] = lg2f(q[t]);         // finite: q in (0,1]
        m0s[t]  = __fdividef(m0, s[t]);   // scaled-space initial state
    }

    // ============ ALL SCAN WORK IN SCALED SPACE m' = m/s ============
    // recurrence becomes m' = x + q*m'  (no s multiplies anywhere)

    // ---- phase 1: coalesced loads + per-group affine reduction ----
    // warp-tile layout: float4 index g(i) = warp*128 + i*32 + lane
    float c[4][ITERS];                // [rate][iter] scaled group contributions
    #pragma unroll
    for (int i = 0; i < ITERS; i++) {
        const float4 v = __ldg(xrow4 + warp * 128 + i * 32 + lane);
        #pragma unroll
        for (int t = 0; t < 4; t++) {
            float cc = v.x;
            cc = fmaf(q[t], cc, v.y);
            cc = fmaf(q[t], cc, v.z);
            cc = fmaf(q[t], cc, v.w);
            c[t][i] = cc;
        }
    }

    // ---- phase 2: per rate, 4 independent warp scans over lanes ----
    float E[4][ITERS];     // exclusive within-iteration prefix (scaled)
    float T[4][ITERS];     // iteration-tile totals (broadcast, scaled)
    float B[4];            // A^32 = q^128 (tile multiplier)
    #pragma unroll
    for (int t = 0; t < 4; t++) {
        float S0 = c[t][0], S1 = c[t][1], S2 = c[t][2], S3 = c[t][3];
        float P = A[t];
        #pragma unroll
        for (int o = 1; o < 32; o <<= 1) {
            float v0 = __shfl_up_sync(0xffffffffu, S0, o);
            float v1 = __shfl_up_sync(0xffffffffu, S1, o);
            float v2 = __shfl_up_sync(0xffffffffu, S2, o);
            float v3 = __shfl_up_sync(0xffffffffu, S3, o);
            if (lane >= o) {
                S0 = fmaf(P, v0, S0); S1 = fmaf(P, v1, S1);
                S2 = fmaf(P, v2, S2); S3 = fmaf(P, v3, S3);
            }
            P *= P;                   // after loop: P = A^32
        }
        B[t] = P;
        E[t][0] = __shfl_up_sync(0xffffffffu, S0, 1);
        E[t][1] = __shfl_up_sync(0xffffffffu, S1, 1);
        E[t][2] = __shfl_up_sync(0xffffffffu, S2, 1);
        E[t][3] = __shfl_up_sync(0xffffffffu, S3, 1);
        if (lane == 0) { E[t][0] = 0.f; E[t][1] = 0.f; E[t][2] = 0.f; E[t][3] = 0.f; }
        T[t][0] = __shfl_sync(0xffffffffu, S0, 31);
        T[t][1] = __shfl_sync(0xffffffffu, S1, 31);
        T[t][2] = __shfl_sync(0xffffffffu, S2, 31);
        T[t][3] = __shfl_sync(0xffffffffu, S3, 31);
        // warp-tile total U = T3 + B*T2 + B^2*T1 + B^3*T0
        float U = fmaf(P, fmaf(P, fmaf(P, T[t][0], T[t][1]), T[t][2]), T[t][3]);
        if (lane == 0) warp_tot[t][warp] = U;
    }
    __syncthreads();

    // ---- phase 3: block scan over 16 warp totals per rate (mult D=B^4) ----
    // Dt = q^512 may underflow to 0 for fast rates; numerically correct.
    if (warp == 0) {
        float W[4], Pq[4];
        #pragma unroll
        for (int t = 0; t < 4; t++) {
            W[t]  = (lane < NWARPS) ? warp_tot[t][lane] : 0.0f;
            float B2 = B[t] * B[t];
            Pq[t] = B2 * B2;          // D = q^512 (may flush to 0: OK)
        }
        #pragma unroll
        for (int o = 1; o < NWARPS; o <<= 1) {
            #pragma unroll
            for (int t = 0; t < 4; t++) {
                float v = __shfl_up_sync(0xffffffffu, W[t], o);
                if (lane >= o) W[t] = fmaf(Pq[t], v, W[t]);
                Pq[t] *= Pq[t];
            }
        }
        #pragma unroll
        for (int t = 0; t < 4; t++) {
            float Wex = __shfl_up_sync(0xffffffffu, W[t], 1);
            if (lane == 0) Wex = 0.0f;
            if (lane < NWARPS) warp_excl[t][lane] = Wex;
        }
    }
    __syncthreads();

    // ---- collapse carry state: C0[t][i] = scaled carry entering my group ----
    float C0[4][ITERS];
    #pragma unroll
    for (int t = 0; t < 4; t++) {
        const float Bt = B[t];
        const float Dw = ex2f((float)(warp * 512) * lg2q[t]);  // q^(512*warp)
        float M0 = fmaf(Dw, m0s[t], warp_excl[t][warp]);
        float M1 = fmaf(Bt, M0, T[t][0]);
        float M2 = fmaf(Bt, M1, T[t][1]);
        float M3 = fmaf(Bt, M2, T[t][2]);
        const float Al = ex2f((float)(lane * 4) * lg2q[t]);
        C0[t][0] = fmaf(Al, M0, E[t][0]);
        C0[t][1] = fmaf(Al, M1, E[t][1]);
        C0[t][2] = fmaf(Al, M2, E[t][2]);
        C0[t][3] = fmaf(Al, M3, E[t][3]);
    }

    const float nalpha = -alpha;

    // ---- phase 4: fused emit — one x load per group, 4 rates interleaved ----
    // scaled recurrence: cy' = xi + q*cy';  u = EPS + s*cy' (one FMA each)
    float4* __restrict__ obase = reinterpret_cast<float4*>(out) +
        ((size_t)b * 4 * nbands + f) * NF4;
    const size_t ostride = (size_t)nbands * NF4;     // float4 per rate plane

    #pragma unroll
    for (int i = 0; i < ITERS; i++) {
        const int g = warp * 128 + i * 32 + lane;
        const float4 xi4 = __ldg(xrow4 + g);         // single load per group

        #pragma unroll
        for (int tv = 0; tv < 4; tv++) {
            const float st = s[tv];
            const float qt = q[tv];
            float cy = C0[tv][i];
            float4 o4;
            #pragma unroll
            for (int k = 0; k < 4; k++) {
                const float xi = (&xi4.x)[k];
                cy = fmaf(qt, cy, xi);                              // scaled EMA
                const float u  = fmaf(st, cy, 1e-5f);               // EPS + m
                // w = x * (EPS+m)^-a / d  (1/d folded into the exponent)
                const float w  = xi * ex2f(fmaf(nalpha, lg2f(u), nl2d));
                const float zp = lg2f(1.0f + w);
                // out = z' * (G0 + G1 z' + ... + G4 z'^4)   (drcr folded in)
                float p = fmaf(G4, zp, G3);
                p = fmaf(p, zp, G2);
                p = fmaf(p, zp, G1);
                p = fmaf(p, zp, G0);
                (&o4.x)[k] = zp * p;                   // d^r * expm1(r ln(1+w))
            }
            obase[(size_t)tv * ostride + g] = o4;      // coalesced STG.128
        }
    }
}

extern "C" void kernel_launch(void* const* d_in, const int* in_sizes, int n_in,
                              void* d_out, int out_size)
{
    const float* x  = (const float*)d_in[0];
    const float* la = (const float*)d_in[1];
    const float* ld = (const float*)d_in[2];
    const float* lr = (const float*)d_in[3];
    float* out = (float*)d_out;

    const int nbands = in_sizes[1];                 // 128
    const int rows   = in_sizes[0] / N_TIME;        // B * F = 1024

    // s = (sqrt(1 + 4 t^2) - 1) / (2 t^2), computed in double on host
    const double tvals[4] = {2.0, 8.0, 32.0, 128.0};
    float ss[4];
    for (int i = 0; i < 4; i++) {
        double t = tvals[i];
        ss[i] = (float)((sqrt(1.0 + 4.0 * t * t) - 1.0) / (2.0 * t * t));
    }
    float4 sv = make_float4(ss[0], ss[1], ss[2], ss[3]);

    mrpcen_kernel<<<rows, THREADS>>>(x, la, ld, lr, out, sv, nbands);
}